// round 1
// baseline (speedup 1.0000x reference)
#include <cuda_runtime.h>
#include <cuda_bf16.h>

// Problem dims (fixed by the reference)
#define BDIM 32
#define SDIM 128
#define EDIM 512
#define FDIM 2048

// Scratch for the F-wide hidden activation h = x@W1 + b1  (32*128*2048 fp32 = 33.5 MB)
__device__ float g_H[(size_t)BDIM * SDIM * FDIM];

// ---------------------------------------------------------------------------
// GEMM1: for each s: H[b,s,f] = sum_e x[b,s,e] * W1[s,e,f] + b1[s,f]
// M=32 (b), N=2048 (f), K=512 (e). Tile BM=32, BN=128, BK=32, 256 threads,
// 4x4 microtile per thread.
// ---------------------------------------------------------------------------
__global__ __launch_bounds__(256) void gemm1_kernel(
    const float* __restrict__ x, const float* __restrict__ W1,
    const float* __restrict__ b1)
{
    const int s  = blockIdx.y;
    const int n0 = blockIdx.x * 128;

    __shared__ float As[32][36];   // [k][m], row stride 36 floats (144B, 16B-aligned)
    __shared__ float Bs[32][128];  // [k][n]

    const int tid  = threadIdx.x;
    const int tcol = tid & 31;   // n-direction (x4)
    const int trow = tid >> 5;   // m-direction (x4)

    float acc[4][4];
#pragma unroll
    for (int i = 0; i < 4; i++)
#pragma unroll
        for (int j = 0; j < 4; j++) acc[i][j] = 0.0f;

    // A-load mapping: 32 b-rows x 8 float4 along k  (256 float4)
    const int la_b = tid >> 3;        // 0..31
    const int la_k = (tid & 7) * 4;   // 0..28
    // B-load mapping: per iter i, row k = lb_k + i*8, 32 float4 along n
    const int lb_n = (tid & 31) * 4;
    const int lb_k = tid >> 5;        // 0..7

    for (int k0 = 0; k0 < EDIM; k0 += 32) {
        float4 av = *reinterpret_cast<const float4*>(
            x + ((size_t)la_b * SDIM + s) * EDIM + k0 + la_k);
        As[la_k + 0][la_b] = av.x;
        As[la_k + 1][la_b] = av.y;
        As[la_k + 2][la_b] = av.z;
        As[la_k + 3][la_b] = av.w;

#pragma unroll
        for (int i = 0; i < 4; i++) {
            const int k = lb_k + i * 8;
            *reinterpret_cast<float4*>(&Bs[k][lb_n]) =
                *reinterpret_cast<const float4*>(
                    W1 + ((size_t)s * EDIM + k0 + k) * FDIM + n0 + lb_n);
        }
        __syncthreads();

#pragma unroll
        for (int kk = 0; kk < 32; kk++) {
            const float4 a = *reinterpret_cast<const float4*>(&As[kk][trow * 4]);
            const float4 b = *reinterpret_cast<const float4*>(&Bs[kk][tcol * 4]);
            acc[0][0] += a.x * b.x; acc[0][1] += a.x * b.y; acc[0][2] += a.x * b.z; acc[0][3] += a.x * b.w;
            acc[1][0] += a.y * b.x; acc[1][1] += a.y * b.y; acc[1][2] += a.y * b.z; acc[1][3] += a.y * b.w;
            acc[2][0] += a.z * b.x; acc[2][1] += a.z * b.y; acc[2][2] += a.z * b.z; acc[2][3] += a.z * b.w;
            acc[3][0] += a.w * b.x; acc[3][1] += a.w * b.y; acc[3][2] += a.w * b.z; acc[3][3] += a.w * b.w;
        }
        __syncthreads();
    }

    // Epilogue: +b1, write H
#pragma unroll
    for (int i = 0; i < 4; i++) {
        const int b = trow * 4 + i;
        const int n = n0 + tcol * 4;
        const float* bias = b1 + (size_t)s * FDIM + n;
        float4 o;
        o.x = acc[i][0] + bias[0];
        o.y = acc[i][1] + bias[1];
        o.z = acc[i][2] + bias[2];
        o.w = acc[i][3] + bias[3];
        *reinterpret_cast<float4*>(g_H + ((size_t)b * SDIM + s) * FDIM + n) = o;
    }
}

// ---------------------------------------------------------------------------
// GEMM2: for each s: y[b,s,e] = sum_f H[b,s,f] * W2[s,f,e] + b2[s,e] + x[b,s,e]
// M=32 (b), N=512 (e), K=2048 (f). Same tiling. Writes pre-LN y into d_out.
// ---------------------------------------------------------------------------
__global__ __launch_bounds__(256) void gemm2_kernel(
    const float* __restrict__ W2, const float* __restrict__ b2,
    const float* __restrict__ x, float* __restrict__ out)
{
    const int s  = blockIdx.y;
    const int n0 = blockIdx.x * 128;

    __shared__ float As[32][36];
    __shared__ float Bs[32][128];

    const int tid  = threadIdx.x;
    const int tcol = tid & 31;
    const int trow = tid >> 5;

    float acc[4][4];
#pragma unroll
    for (int i = 0; i < 4; i++)
#pragma unroll
        for (int j = 0; j < 4; j++) acc[i][j] = 0.0f;

    const int la_b = tid >> 3;
    const int la_k = (tid & 7) * 4;
    const int lb_n = (tid & 31) * 4;
    const int lb_k = tid >> 5;

    for (int k0 = 0; k0 < FDIM; k0 += 32) {
        float4 av = *reinterpret_cast<const float4*>(
            g_H + ((size_t)la_b * SDIM + s) * FDIM + k0 + la_k);
        As[la_k + 0][la_b] = av.x;
        As[la_k + 1][la_b] = av.y;
        As[la_k + 2][la_b] = av.z;
        As[la_k + 3][la_b] = av.w;

#pragma unroll
        for (int i = 0; i < 4; i++) {
            const int k = lb_k + i * 8;
            *reinterpret_cast<float4*>(&Bs[k][lb_n]) =
                *reinterpret_cast<const float4*>(
                    W2 + ((size_t)s * FDIM + k0 + k) * EDIM + n0 + lb_n);
        }
        __syncthreads();

#pragma unroll
        for (int kk = 0; kk < 32; kk++) {
            const float4 a = *reinterpret_cast<const float4*>(&As[kk][trow * 4]);
            const float4 b = *reinterpret_cast<const float4*>(&Bs[kk][tcol * 4]);
            acc[0][0] += a.x * b.x; acc[0][1] += a.x * b.y; acc[0][2] += a.x * b.z; acc[0][3] += a.x * b.w;
            acc[1][0] += a.y * b.x; acc[1][1] += a.y * b.y; acc[1][2] += a.y * b.z; acc[1][3] += a.y * b.w;
            acc[2][0] += a.z * b.x; acc[2][1] += a.z * b.y; acc[2][2] += a.z * b.z; acc[2][3] += a.z * b.w;
            acc[3][0] += a.w * b.x; acc[3][1] += a.w * b.y; acc[3][2] += a.w * b.z; acc[3][3] += a.w * b.w;
        }
        __syncthreads();
    }

    // Epilogue: +b2 + residual x, write y (pre-LN) to out
#pragma unroll
    for (int i = 0; i < 4; i++) {
        const int b = trow * 4 + i;
        const int n = n0 + tcol * 4;
        const size_t xoff = ((size_t)b * SDIM + s) * EDIM + n;
        const float4 xr = *reinterpret_cast<const float4*>(x + xoff);
        const float* bias = b2 + (size_t)s * EDIM + n;
        float4 o;
        o.x = acc[i][0] + bias[0] + xr.x;
        o.y = acc[i][1] + bias[1] + xr.y;
        o.z = acc[i][2] + bias[2] + xr.z;
        o.w = acc[i][3] + bias[3] + xr.w;
        *reinterpret_cast<float4*>(out + xoff) = o;
    }
}

// ---------------------------------------------------------------------------
// LayerNorm (in place): one block per (b,s) row of 512 elems. 128 thr x float4.
// ---------------------------------------------------------------------------
__global__ __launch_bounds__(128) void ln_kernel(
    float* __restrict__ io, const float* __restrict__ gamma,
    const float* __restrict__ beta)
{
    const int row = blockIdx.x;
    float* p = io + (size_t)row * EDIM;
    const int t = threadIdx.x;

    float4 v = reinterpret_cast<float4*>(p)[t];
    float s1 = v.x + v.y + v.z + v.w;
    float s2 = v.x * v.x + v.y * v.y + v.z * v.z + v.w * v.w;

#pragma unroll
    for (int o = 16; o > 0; o >>= 1) {
        s1 += __shfl_xor_sync(0xffffffffu, s1, o);
        s2 += __shfl_xor_sync(0xffffffffu, s2, o);
    }
    __shared__ float sh1[4], sh2[4];
    if ((t & 31) == 0) { sh1[t >> 5] = s1; sh2[t >> 5] = s2; }
    __syncthreads();
    s1 = sh1[0] + sh1[1] + sh1[2] + sh1[3];
    s2 = sh2[0] + sh2[1] + sh2[2] + sh2[3];

    const float mu  = s1 * (1.0f / EDIM);
    const float var = s2 * (1.0f / EDIM) - mu * mu;
    const float inv = rsqrtf(var + 1e-5f);

    const float4 g  = reinterpret_cast<const float4*>(gamma)[t];
    const float4 be = reinterpret_cast<const float4*>(beta)[t];
    float4 o;
    o.x = (v.x - mu) * inv * g.x + be.x;
    o.y = (v.y - mu) * inv * g.y + be.y;
    o.z = (v.z - mu) * inv * g.z + be.z;
    o.w = (v.w - mu) * inv * g.w + be.w;
    reinterpret_cast<float4*>(p)[t] = o;
}

extern "C" void kernel_launch(void* const* d_in, const int* in_sizes, int n_in,
                              void* d_out, int out_size)
{
    const float* x     = (const float*)d_in[0];
    const float* W1    = (const float*)d_in[1];
    const float* b1    = (const float*)d_in[2];
    const float* W2    = (const float*)d_in[3];
    const float* b2    = (const float*)d_in[4];
    const float* gamma = (const float*)d_in[5];
    const float* beta  = (const float*)d_in[6];
    float* out = (float*)d_out;

    gemm1_kernel<<<dim3(FDIM / 128, SDIM), 256>>>(x, W1, b1);
    gemm2_kernel<<<dim3(EDIM / 128, SDIM), 256>>>(W2, b2, x, out);
    ln_kernel<<<BDIM * SDIM, 128>>>(out, gamma, beta);
}